// round 16
// baseline (speedup 1.0000x reference)
#include <cuda_runtime.h>
#include <cuda_fp16.h>
#include <cstdint>

// ---------------------------------------------------------------------------
// SemanticLSTM: B=256, T=80, E=512, I=H=1024, L=300, F=2048, V=32000
// Recurrence: fp16 mma.sync split-K=2, 128x128 tiles, PDL (R12 structure —
// proven optimum; R13 tail-fusion, R14 4-stage, R15 vec-transpose all showed
// no gain). R16: gather writes fp16 directly (drops conv16(emb)); PDL applied
// to the whole prologue chain to hide launch gaps.
// ---------------------------------------------------------------------------

#define BB 256
#define TT 80
#define EE 512
#define II 1024
#define HH 1024
#define LL 300
#define FF 2048

// fp32 scratch
__device__ float g_bufA[BB * 4 * II];
__device__ float g_base[BB * 4 * HH];
__device__ float g_SH  [BB * 4 * II];
__device__ float g_c   [BB * HH];
// split-K partial buffers
__device__ __align__(16) float g_p0[BB * 4 * HH];
__device__ __align__(16) float g_p1[BB * 4 * HH];

// fp16 activation buffers
__device__ __half g_h16  [BB * HH];
__device__ __half g_x16  [BB * 4 * II];
__device__ __half g_emb16[BB * EE];
__device__ __half g_cnn16[BB * FF];
__device__ __half g_bufB16[BB * 4 * II];
// transposed fp16 weights
__device__ __half g_UaT[4 * 1024 * 1024];
__device__ __half g_UcT[4 * 1024 * 1024];
__device__ __half g_WaT[4 * 1024 * 512];
__device__ __half g_WcT[4 * 1024 * 1024];
__device__ __half g_CaT[4 * 1024 * 2048];
__device__ __half g_CcT[4 * 1024 * 1024];

// ---------------------------------------------------------------------------
// helpers
// ---------------------------------------------------------------------------
__device__ __forceinline__ uint32_t smem_u32(const void* p) {
    uint32_t a;
    asm("{ .reg .u64 t; cvta.to.shared.u64 t, %1; cvt.u32.u64 %0, t; }" : "=r"(a) : "l"(p));
    return a;
}
__device__ __forceinline__ void cpa16(uint32_t d, const void* s) {
    asm volatile("cp.async.cg.shared.global [%0], [%1], 16;" :: "r"(d), "l"(s));
}
__device__ __forceinline__ void cpa_commit() { asm volatile("cp.async.commit_group;"); }
template <int N>
__device__ __forceinline__ void cpa_wait() {
    asm volatile("cp.async.wait_group %0;" :: "n"(N) : "memory");
}
__device__ __forceinline__ void ldm_x4(uint32_t* r, uint32_t a) {
    asm volatile("ldmatrix.sync.aligned.m8n8.x4.shared.b16 {%0,%1,%2,%3}, [%4];"
                 : "=r"(r[0]), "=r"(r[1]), "=r"(r[2]), "=r"(r[3]) : "r"(a));
}
__device__ __forceinline__ void mma16816(float* d, const uint32_t* a, uint32_t b0, uint32_t b1) {
    asm volatile(
        "mma.sync.aligned.m16n8k16.row.col.f32.f16.f16.f32 "
        "{%0,%1,%2,%3},{%4,%5,%6,%7},{%8,%9},{%0,%1,%2,%3};"
        : "+f"(d[0]), "+f"(d[1]), "+f"(d[2]), "+f"(d[3])
        : "r"(a[0]), "r"(a[1]), "r"(a[2]), "r"(a[3]), "r"(b0), "r"(b1));
}
__device__ __forceinline__ void pdl_wait()    { asm volatile("griddepcontrol.wait;" ::: "memory"); }
__device__ __forceinline__ void pdl_trigger() { asm volatile("griddepcontrol.launch_dependents;"); }

// ---------------------------------------------------------------------------
// zero state
// ---------------------------------------------------------------------------
__global__ __launch_bounds__(256) void zero_hc_kernel() {
    int idx = blockIdx.x * 256 + threadIdx.x;
    if (idx < BB * HH) {
        g_c[idx] = 0.f;
        g_h16[idx] = __float2half(0.f);
    }
    pdl_trigger();
}

// ---------------------------------------------------------------------------
// gather emb16 = fp16(embed[captions[:,0]])  (int64/int32 robust)
// ---------------------------------------------------------------------------
__global__ __launch_bounds__(256) void gather_emb_kernel(const void* __restrict__ caps,
                                                         const float* __restrict__ embed) {
    pdl_wait();
    __shared__ int is64;
    if (threadIdx.x == 0) {
        const int* p = (const int*)caps;
        int z = 1;
        for (int k = 0; k < 16; k++)
            if (p[2 * k + 1] != 0) z = 0;
        is64 = z;
    }
    __syncthreads();
    int idx = blockIdx.x * 256 + threadIdx.x;
    if (idx < BB * (EE / 4)) {
        int b  = idx / (EE / 4);
        int e4 = idx % (EE / 4);
        long long cap;
        if (is64) cap = ((const long long*)caps)[(long long)b * TT];
        else      cap = (long long)((const int*)caps)[b * TT];
        float4 v = ((const float4*)embed)[cap * (EE / 4) + e4];
        *(__half2*)&g_emb16[idx * 4]     = __floats2half2_rn(v.x, v.y);
        *(__half2*)&g_emb16[idx * 4 + 2] = __floats2half2_rn(v.z, v.w);
    }
    pdl_trigger();
}

// ---------------------------------------------------------------------------
// elementwise fp32 -> fp16
// ---------------------------------------------------------------------------
__global__ __launch_bounds__(256) void conv16_kernel(const float* __restrict__ s,
                                                     __half* __restrict__ d) {
    pdl_wait();
    int idx = (blockIdx.x * 256 + threadIdx.x) * 4;
    float4 v = *(const float4*)&s[idx];
    *(__half2*)&d[idx]     = __floats2half2_rn(v.x, v.y);
    *(__half2*)&d[idx + 2] = __floats2half2_rn(v.z, v.w);
    pdl_trigger();
}

// ---------------------------------------------------------------------------
// transpose + fp16: dst[g, x, y] = fp16(src[g, y, x]); src (g, K, 1024)
// ---------------------------------------------------------------------------
__global__ __launch_bounds__(256) void convTK_kernel(const float* __restrict__ src,
                                                     __half* __restrict__ dst, int K) {
    pdl_wait();
    __shared__ float t[32][33];
    int g  = blockIdx.z;
    int x0 = blockIdx.x * 32;
    int y0 = blockIdx.y * 32;
    int tx = threadIdx.x & 31, ty = threadIdx.x >> 5;
    const float* s = src + (size_t)g * K * 1024;
#pragma unroll
    for (int k = 0; k < 4; k++)
        t[ty + k * 8][tx] = s[(size_t)(y0 + ty + k * 8) * 1024 + x0 + tx];
    __syncthreads();
    __half* o = dst + (size_t)g * 1024 * K;
#pragma unroll
    for (int k = 0; k < 4; k++)
        o[(size_t)(x0 + ty + k * 8) * K + y0 + tx] = __float2half(t[tx][ty + k * 8]);
    pdl_trigger();
}

// ---------------------------------------------------------------------------
// fp32 prologue SGEMM (3 launches: the K=300 GEMMs)
// mode 0: C=acc (fp32) ; mode 1: Ch=fp16(acc * Z)
// ---------------------------------------------------------------------------
#define BM 64
#define BN 128
#define BK 16

__global__ __launch_bounds__(256) void gemm4_kernel(
    const float* __restrict__ A, int lda, int agoff,
    const float* __restrict__ W, int K,
    const float* Z, float* C, __half* Ch, int mode)
{
    pdl_wait();
    const int N = 1024;
    const int g  = blockIdx.z;
    const int bx = blockIdx.x;
    const int by = blockIdx.y;

    __shared__ float As[BK][BM];
    __shared__ float Bs[BK][BN];

    const int tid = threadIdx.x;
    const int tx  = tid & 15;
    const int ty  = tid >> 4;

    const float* Ag = A + (size_t)g * agoff;
    const float* Wg = W + (size_t)g * K * N + bx * BN;

    float acc[4][8];
#pragma unroll
    for (int i = 0; i < 4; i++)
#pragma unroll
        for (int j = 0; j < 8; j++) acc[i][j] = 0.f;

    const int arow = tid >> 2;
    const int ac   = (tid & 3) * 4;

    for (int kk = 0; kk < K; kk += BK) {
        {
            const int m = by * BM + arow;
            const float* ap = Ag + (size_t)m * lda + kk + ac;
#pragma unroll
            for (int j = 0; j < 4; j++) {
                float v = (kk + ac + j < K) ? ap[j] : 0.f;
                As[ac + j][arow] = v;
            }
        }
#pragma unroll
        for (int r = 0; r < 2; r++) {
            int idx  = tid + r * 256;
            int brow = idx >> 5;
            int bc   = (idx & 31) * 4;
            int kg   = kk + brow;
            float4 v;
            if (kg < K) v = *(const float4*)(Wg + (size_t)kg * N + bc);
            else        v = make_float4(0.f, 0.f, 0.f, 0.f);
            *(float4*)&Bs[brow][bc] = v;
        }
        __syncthreads();

#pragma unroll
        for (int k = 0; k < BK; k++) {
            float4 av = *(const float4*)&As[k][ty * 4];
            float4 b0 = *(const float4*)&Bs[k][tx * 8];
            float4 b1 = *(const float4*)&Bs[k][tx * 8 + 4];
            float a[4] = {av.x, av.y, av.z, av.w};
            float b[8] = {b0.x, b0.y, b0.z, b0.w, b1.x, b1.y, b1.z, b1.w};
#pragma unroll
            for (int i = 0; i < 4; i++)
#pragma unroll
                for (int j = 0; j < 8; j++)
                    acc[i][j] = fmaf(a[i], b[j], acc[i][j]);
        }
        __syncthreads();
    }

#pragma unroll
    for (int i = 0; i < 4; i++) {
        const int m = by * BM + ty * 4 + i;
        const int n0 = bx * BN + tx * 8;
        size_t row = (size_t)m * 4096 + (size_t)g * 1024 + n0;
#pragma unroll
        for (int j = 0; j < 8; j++) {
            float v = acc[i][j];
            if (mode == 1) Ch[row + j] = __float2half(v * Z[row + j]);
            else           C[row + j]  = v;
        }
    }
    pdl_trigger();
}

// ---------------------------------------------------------------------------
// shared TC tile geometry — 3-stage pipeline (R12, proven optimum)
// ---------------------------------------------------------------------------
#define ASTRIDE  144                     // bytes per smem row (64 fp16 + pad)
#define A_TILE_B (128 * ASTRIDE)         // 18432
#define B_TILE_B (128 * ASTRIDE)         // 18432
#define STAGE_B  (A_TILE_B + B_TILE_B)   // 36864
#define NSTAGE   3
#define MM_SMEM  (NSTAGE * STAGE_B)      // 110592

__device__ __forceinline__ void load_stage(
    uint32_t sa, uint32_t sb,
    const __half* __restrict__ A, int lda,
    const __half* __restrict__ B, int ldb,
    int k0, int tid)
{
#pragma unroll
    for (int r = 0; r < 4; r++) {
        int id  = tid + (r << 8);
        int row = id >> 3;
        int cb  = id & 7;
        uint32_t d = sa + row * ASTRIDE + cb * 16;
        size_t  sp = (size_t)row * lda + k0 + cb * 8;
        cpa16(d, A + sp);
    }
#pragma unroll
    for (int r = 0; r < 4; r++) {
        int id  = tid + (r << 8);
        int row = id >> 3;
        int cb  = id & 7;
        uint32_t d = sb + row * ASTRIDE + cb * 16;
        size_t  sp = (size_t)row * ldb + k0 + cb * 8;
        cpa16(d, B + sp);
    }
}

__device__ __forceinline__ void chunk_mma(uint32_t aCur, uint32_t bCur, float acc[2][8][4]) {
#pragma unroll
    for (int ks = 0; ks < 4; ks++) {
        uint32_t a[2][4], b[4][4];
        const uint32_t ka = aCur + ks * 32;
        const uint32_t kb = bCur + ks * 32;
        ldm_x4(a[0], ka);
        ldm_x4(a[1], ka + 16 * ASTRIDE);
        ldm_x4(b[0], kb);
        ldm_x4(b[1], kb + 16 * ASTRIDE);
        ldm_x4(b[2], kb + 32 * ASTRIDE);
        ldm_x4(b[3], kb + 48 * ASTRIDE);
#pragma unroll
        for (int im = 0; im < 2; im++)
#pragma unroll
            for (int jn = 0; jn < 8; jn++) {
                const int jp = jn >> 1, q = (jn & 1) * 2;
                mma16816(acc[im][jn], a[im], b[jp][q], b[jp][q + 1]);
            }
    }
}

// 3-stage mainloop: preload 2 chunks; per chunk: wait, ONE sync, prefetch c+2, mma
__device__ __forceinline__ void mainloop3(
    uint32_t sbase, const __half* Ap, int lda, const __half* Bp, int ldb,
    int NC, int tid, uint32_t aBase, uint32_t bBase, float acc[2][8][4])
{
    load_stage(sbase,           sbase + A_TILE_B,           Ap, lda, Bp, ldb, 0,  tid);
    cpa_commit();
    load_stage(sbase + STAGE_B, sbase + STAGE_B + A_TILE_B, Ap, lda, Bp, ldb, 64, tid);
    cpa_commit();

    for (int c = 0; c < NC; c++) {
        if (c + 1 < NC) cpa_wait<1>(); else cpa_wait<0>();
        __syncthreads();
        if (c + 2 < NC) {
            const uint32_t s2 = ((c + 2) % NSTAGE) * STAGE_B;
            load_stage(sbase + s2, sbase + s2 + A_TILE_B, Ap, lda, Bp, ldb, (c + 2) * 64, tid);
            cpa_commit();
        }
        const uint32_t soff = (c % NSTAGE) * STAGE_B;
        chunk_mma(aBase + soff, bBase + soff, acc);
    }
}

// ---------------------------------------------------------------------------
// Recurrence split-K GEMM: grid (8 nx, 4 {my,kh}, 4 g) = 128 CTAs
// ---------------------------------------------------------------------------
__global__ __launch_bounds__(256, 1) void tcsplit_kernel(
    const __half* __restrict__ A, int lda, int agoff,
    const __half* __restrict__ B,
    float* __restrict__ part0, float* __restrict__ part1)
{
    extern __shared__ char dsm[];
    const uint32_t sbase = smem_u32(dsm);

    const int g    = blockIdx.z;
    const int nx   = blockIdx.x;
    const int my   = blockIdx.y >> 1;
    const int kh   = blockIdx.y & 1;
    const int tid  = threadIdx.x;
    const int lane = tid & 31;
    const int warp = tid >> 5;
    const int wm   = warp & 3;
    const int wn   = warp >> 2;

    pdl_wait();

    const __half* Ap = A + (size_t)g * agoff + (size_t)(my * 128) * lda + kh * 512;
    const __half* Bp = B + ((size_t)g * 1024 + nx * 128) * 1024 + kh * 512;
    float* outP = kh ? part1 : part0;

    float acc[2][8][4];
#pragma unroll
    for (int i = 0; i < 2; i++)
#pragma unroll
        for (int j = 0; j < 8; j++)
#pragma unroll
            for (int k = 0; k < 4; k++) acc[i][j][k] = 0.f;

    const int rin  = lane & 7;
    const int quad = lane >> 3;
    const uint32_t aoff = ((quad & 1) * 8 + rin) * ASTRIDE + (quad >> 1) * 16;
    const uint32_t boff = ((quad >> 1) * 8 + rin) * ASTRIDE + (quad & 1) * 16;
    const uint32_t aBase = sbase + wm * 32 * ASTRIDE + aoff;
    const uint32_t bBase = sbase + A_TILE_B + wn * 64 * ASTRIDE + boff;

    mainloop3(sbase, Ap, lda, Bp, 1024, 8, tid, aBase, bBase, acc);

#pragma unroll
    for (int im = 0; im < 2; im++) {
        const int m0 = my * 128 + wm * 32 + im * 16 + (lane >> 2);
#pragma unroll
        for (int jn = 0; jn < 8; jn++) {
            const int n0 = nx * 128 + wn * 64 + jn * 8 + (lane & 3) * 2;
            const size_t p0 = (size_t)m0 * 4096 + (size_t)g * 1024 + n0;
            const size_t p1 = p0 + 8 * 4096;
            const float* a = acc[im][jn];
            *(float2*)&outP[p0] = make_float2(a[0], a[1]);
            *(float2*)&outP[p1] = make_float2(a[2], a[3]);
        }
    }
    pdl_trigger();
}

// ---------------------------------------------------------------------------
// Prologue TC GEMM: runtime K (mult of 64, NC>=8). grid (8 nx, 2 my, 4 g).
// mode 0: C=acc ; mode 2: C=acc+Z+bias.
// ---------------------------------------------------------------------------
__global__ __launch_bounds__(256, 1) void tcpro_kernel(
    const __half* __restrict__ A, int lda, int agoff,
    const __half* __restrict__ BT, int K,
    const float* Z, const float* __restrict__ bias,
    float* __restrict__ outF, int mode)
{
    extern __shared__ char dsm[];
    const uint32_t sbase = smem_u32(dsm);

    const int g    = blockIdx.z;
    const int nx   = blockIdx.x;
    const int my   = blockIdx.y;
    const int tid  = threadIdx.x;
    const int lane = tid & 31;
    const int warp = tid >> 5;
    const int wm   = warp & 3;
    const int wn   = warp >> 2;

    pdl_wait();

    const __half* Ap = A + (size_t)g * agoff + (size_t)(my * 128) * lda;
    const __half* Bp = BT + ((size_t)g * 1024 + nx * 128) * K;

    float acc[2][8][4];
#pragma unroll
    for (int i = 0; i < 2; i++)
#pragma unroll
        for (int j = 0; j < 8; j++)
#pragma unroll
            for (int k = 0; k < 4; k++) acc[i][j][k] = 0.f;

    const int rin  = lane & 7;
    const int quad = lane >> 3;
    const uint32_t aoff = ((quad & 1) * 8 + rin) * ASTRIDE + (quad >> 1) * 16;
    const uint32_t boff = ((quad >> 1) * 8 + rin) * ASTRIDE + (quad & 1) * 16;
    const uint32_t aBase = sbase + wm * 32 * ASTRIDE + aoff;
    const uint32_t bBase = sbase + A_TILE_B + wn * 64 * ASTRIDE + boff;

    mainloop3(sbase, Ap, lda, Bp, K, K >> 6, tid, aBase, bBase, acc);

#pragma unroll
    for (int im = 0; im < 2; im++) {
        const int m0 = my * 128 + wm * 32 + im * 16 + (lane >> 2);
#pragma unroll
        for (int jn = 0; jn < 8; jn++) {
            const int n0 = nx * 128 + wn * 64 + jn * 8 + (lane & 3) * 2;
            const size_t p0 = (size_t)m0 * 4096 + (size_t)g * 1024 + n0;
            const size_t p1 = p0 + 8 * 4096;
            const float* a = acc[im][jn];
            if (mode == 2) {
                float b0 = bias[g * 1024 + n0], b1 = bias[g * 1024 + n0 + 1];
                *(float2*)&outF[p0] = make_float2(a[0] + Z[p0] + b0, a[1] + Z[p0 + 1] + b1);
                *(float2*)&outF[p1] = make_float2(a[2] + Z[p1] + b0, a[3] + Z[p1 + 1] + b1);
            } else {
                *(float2*)&outF[p0] = make_float2(a[0], a[1]);
                *(float2*)&outF[p1] = make_float2(a[2], a[3]);
            }
        }
    }
    pdl_trigger();
}

// ---------------------------------------------------------------------------
// E1: x16 = fp16((p0 + p1) * SH)
// ---------------------------------------------------------------------------
__global__ __launch_bounds__(256) void e1_kernel() {
    pdl_wait();
    int idx = (blockIdx.x * 256 + threadIdx.x) * 4;
    float4 a = *(const float4*)&g_p0[idx];
    float4 b = *(const float4*)&g_p1[idx];
    float4 s = *(const float4*)&g_SH[idx];
    *(__half2*)&g_x16[idx]     = __floats2half2_rn((a.x + b.x) * s.x, (a.y + b.y) * s.y);
    *(__half2*)&g_x16[idx + 2] = __floats2half2_rn((a.z + b.z) * s.z, (a.w + b.w) * s.w);
    pdl_trigger();
}

// ---------------------------------------------------------------------------
// LSTM gate update (float4): pre = p0+p1+base; updates c, h fp16
// ---------------------------------------------------------------------------
__global__ __launch_bounds__(256) void lstm_gate_kernel(float* out) {
    pdl_wait();
    int idx = (blockIdx.x * 256 + threadIdx.x) * 4;
    int b   = idx >> 10;
    int hh  = idx & 1023;
    size_t off = ((size_t)b << 12) + hh;

    float4 i0 = *(const float4*)&g_p0[off];
    float4 i1 = *(const float4*)&g_p1[off];
    float4 ib = *(const float4*)&g_base[off];
    float4 f0 = *(const float4*)&g_p0[off + 1024];
    float4 f1 = *(const float4*)&g_p1[off + 1024];
    float4 fb = *(const float4*)&g_base[off + 1024];
    float4 o0 = *(const float4*)&g_p0[off + 2048];
    float4 o1 = *(const float4*)&g_p1[off + 2048];
    float4 ob = *(const float4*)&g_base[off + 2048];
    float4 q0 = *(const float4*)&g_p0[off + 3072];
    float4 q1 = *(const float4*)&g_p1[off + 3072];
    float4 qb = *(const float4*)&g_base[off + 3072];
    float4 cc = *(const float4*)&g_c[idx];

    float hv[4];
#pragma unroll
    for (int k = 0; k < 4; k++) {
        float xi = ((const float*)&i0)[k] + ((const float*)&i1)[k] + ((const float*)&ib)[k];
        float xf = ((const float*)&f0)[k] + ((const float*)&f1)[k] + ((const float*)&fb)[k];
        float xo = ((const float*)&o0)[k] + ((const float*)&o1)[k] + ((const float*)&ob)[k];
        float xg = ((const float*)&q0)[k] + ((const float*)&q1)[k] + ((const float*)&qb)[k];
        float ig = 1.f / (1.f + expf(-xi));
        float fg = 1.f / (1.f + expf(-xf));
        float og = 1.f / (1.f + expf(-xo));
        float gg = tanhf(xg);
        float c = fg * ((const float*)&cc)[k] + ig * gg;
        ((float*)&cc)[k] = c;
        hv[k] = og * tanhf(c);
    }
    *(float4*)&g_c[idx] = cc;
    *(__half2*)&g_h16[idx]     = __floats2half2_rn(hv[0], hv[1]);
    *(__half2*)&g_h16[idx + 2] = __floats2half2_rn(hv[2], hv[3]);
    if (out) *(float4*)&out[idx] = make_float4(hv[0], hv[1], hv[2], hv[3]);
    pdl_trigger();
}

// ---------------------------------------------------------------------------
extern "C" void kernel_launch(void* const* d_in, const int* in_sizes, int n_in,
                              void* d_out, int out_size) {
    const void*  caps  = d_in[0];
    const float* cnn   = (const float*)d_in[1];
    const float* sem   = (const float*)d_in[2];
    const float* embed = (const float*)d_in[3];
    const float* Wa    = (const float*)d_in[4];
    const float* Wb    = (const float*)d_in[5];
    const float* Wc    = (const float*)d_in[6];
    const float* Ua    = (const float*)d_in[7];
    const float* Ub    = (const float*)d_in[8];
    const float* Uc    = (const float*)d_in[9];
    const float* Ca    = (const float*)d_in[10];
    const float* Cb    = (const float*)d_in[11];
    const float* Cc    = (const float*)d_in[12];
    const float* bias  = (const float*)d_in[13];

    float *p_bufA, *p_base, *p_SH, *p_p0, *p_p1;
    cudaGetSymbolAddress((void**)&p_bufA, g_bufA);
    cudaGetSymbolAddress((void**)&p_base, g_base);
    cudaGetSymbolAddress((void**)&p_SH,   g_SH);
    cudaGetSymbolAddress((void**)&p_p0,   g_p0);
    cudaGetSymbolAddress((void**)&p_p1,   g_p1);

    __half *p_h16, *p_x16, *p_emb16, *p_cnn16, *p_bufB16;
    __half *p_UaT, *p_UcT, *p_WaT, *p_WcT, *p_CaT, *p_CcT;
    cudaGetSymbolAddress((void**)&p_h16,   g_h16);
    cudaGetSymbolAddress((void**)&p_x16,   g_x16);
    cudaGetSymbolAddress((void**)&p_emb16, g_emb16);
    cudaGetSymbolAddress((void**)&p_cnn16, g_cnn16);
    cudaGetSymbolAddress((void**)&p_bufB16,g_bufB16);
    cudaGetSymbolAddress((void**)&p_UaT, g_UaT);
    cudaGetSymbolAddress((void**)&p_UcT, g_UcT);
    cudaGetSymbolAddress((void**)&p_WaT, g_WaT);
    cudaGetSymbolAddress((void**)&p_WcT, g_WcT);
    cudaGetSymbolAddress((void**)&p_CaT, g_CaT);
    cudaGetSymbolAddress((void**)&p_CcT, g_CcT);

    cudaFuncSetAttribute(tcsplit_kernel, cudaFuncAttributeMaxDynamicSharedMemorySize, MM_SMEM);
    cudaFuncSetAttribute(tcpro_kernel,   cudaFuncAttributeMaxDynamicSharedMemorySize, MM_SMEM);

    // PDL attribute shared by all launches
    cudaLaunchAttribute at[1];
    at[0].id = cudaLaunchAttributeProgrammaticStreamSerialization;
    at[0].val.programmaticStreamSerializationAllowed = 1;

    auto mkcfg = [&](dim3 grid, unsigned smem) {
        cudaLaunchConfig_t c = {};
        c.gridDim = grid; c.blockDim = dim3(256);
        c.dynamicSmemBytes = smem;
        c.attrs = at; c.numAttrs = 1;
        return c;
    };

    cudaLaunchConfig_t cZero = mkcfg(dim3((BB * HH + 255) / 256), 0);
    cudaLaunchConfig_t cGath = mkcfg(dim3((BB * EE / 4 + 255) / 256), 0);
    cudaLaunchConfig_t cCnn  = mkcfg(dim3(BB * FF / 1024), 0);
    cudaLaunchConfig_t cT32  = mkcfg(dim3(32, 32, 4), 0);
    cudaLaunchConfig_t cT16  = mkcfg(dim3(32, 16, 4), 0);
    cudaLaunchConfig_t cT64  = mkcfg(dim3(32, 64, 4), 0);
    cudaLaunchConfig_t cG4   = mkcfg(dim3(1024 / BN, BB / BM, 4), 0);
    cudaLaunchConfig_t cPro  = mkcfg(dim3(8, 2, 4), MM_SMEM);
    cudaLaunchConfig_t cfgG  = mkcfg(dim3(8, 4, 4), MM_SMEM);
    cudaLaunchConfig_t cfgE  = mkcfg(dim3(BB * 4 * II / (256 * 4)), 0);
    cudaLaunchConfig_t cfgL  = mkcfg(dim3(BB * HH / (256 * 4)), 0);

    cudaLaunchKernelEx(&cZero, zero_hc_kernel);
    cudaLaunchKernelEx(&cGath, gather_emb_kernel, caps, embed);
    cudaLaunchKernelEx(&cCnn,  conv16_kernel, cnn, (__half*)p_cnn16);

    // weight transposes + fp16
    cudaLaunchKernelEx(&cT32, convTK_kernel, Ua, (__half*)p_UaT, 1024);
    cudaLaunchKernelEx(&cT32, convTK_kernel, Uc, (__half*)p_UcT, 1024);
    cudaLaunchKernelEx(&cT16, convTK_kernel, Wa, (__half*)p_WaT, 512);
    cudaLaunchKernelEx(&cT32, convTK_kernel, Wc, (__half*)p_WcT, 1024);
    cudaLaunchKernelEx(&cT64, convTK_kernel, Ca, (__half*)p_CaT, 2048);
    cudaLaunchKernelEx(&cT32, convTK_kernel, Cc, (__half*)p_CcT, 1024);

    // prologue: base = (emb@Wa * sem@Wb)@Wc + (cnn@Ca * sem@Cb)@Cc + bias ; SH = sem@Ub
    cudaLaunchKernelEx(&cPro, tcpro_kernel,
                       (const __half*)p_emb16, (int)EE, 0, (const __half*)p_WaT, (int)EE,
                       (const float*)nullptr, (const float*)nullptr, p_bufA, 0);
    cudaLaunchKernelEx(&cG4, gemm4_kernel,
                       sem, (int)LL, 0, Wb, (int)LL,
                       (const float*)p_bufA, (float*)nullptr, (__half*)p_bufB16, 1);
    cudaLaunchKernelEx(&cPro, tcpro_kernel,
                       (const __half*)p_bufB16, 4096, 1024, (const __half*)p_WcT, (int)II,
                       (const float*)nullptr, (const float*)nullptr, p_base, 0);
    cudaLaunchKernelEx(&cPro, tcpro_kernel,
                       (const __half*)p_cnn16, (int)FF, 0, (const __half*)p_CaT, (int)FF,
                       (const float*)nullptr, (const float*)nullptr, p_bufA, 0);
    cudaLaunchKernelEx(&cG4, gemm4_kernel,
                       sem, (int)LL, 0, Cb, (int)LL,
                       (const float*)p_bufA, (float*)nullptr, (__half*)p_bufB16, 1);
    cudaLaunchKernelEx(&cPro, tcpro_kernel,
                       (const __half*)p_bufB16, 4096, 1024, (const __half*)p_CcT, (int)II,
                       (const float*)p_base, bias, p_base, 2);
    cudaLaunchKernelEx(&cG4, gemm4_kernel,
                       sem, (int)LL, 0, Ub, (int)LL,
                       (const float*)nullptr, p_SH, (__half*)nullptr, 0);

    for (int t = 0; t < TT; t++) {
        cudaLaunchKernelEx(&cfgG, tcsplit_kernel,
                           (const __half*)p_h16, 1024, 0, (const __half*)p_UaT, p_p0, p_p1);
        cudaLaunchKernelEx(&cfgE, e1_kernel);
        cudaLaunchKernelEx(&cfgG, tcsplit_kernel,
                           (const __half*)p_x16, 4096, 1024, (const __half*)p_UcT, p_p0, p_p1);
        cudaLaunchKernelEx(&cfgL, lstm_gate_kernel,
                           (float*)(t == TT - 1 ? d_out : nullptr));
    }
}

// round 17
// speedup vs baseline: 1.0199x; 1.0199x over previous
#include <cuda_runtime.h>
#include <cuda_fp16.h>
#include <cstdint>

// ---------------------------------------------------------------------------
// SemanticLSTM: B=256, T=80, E=512, I=H=1024, L=300, F=2048, V=32000
// Recurrence: fp16 mma.sync split-K=2, 128x128 tiles, PDL (R12 structure —
// proven optimum over R13..R16 experiments).
// R17: exact R12 + the two independent K=300 GEMMs (Wb, Cb) merged into ONE
// dual launch (z=8). Bit-identical numerics; saves one serialized kernel.
// ---------------------------------------------------------------------------

#define BB 256
#define TT 80
#define EE 512
#define II 1024
#define HH 1024
#define LL 300
#define FF 2048

// fp32 scratch
__device__ float g_emb [BB * EE];
__device__ float g_bufA[BB * 4 * II];
__device__ float g_base[BB * 4 * HH];
__device__ float g_SH  [BB * 4 * II];
__device__ float g_c   [BB * HH];
// split-K partial buffers (also used as prologue scratch: p0 = Ca output)
__device__ __align__(16) float g_p0[BB * 4 * HH];
__device__ __align__(16) float g_p1[BB * 4 * HH];

// fp16 activation buffers
__device__ __half g_h16  [BB * HH];
__device__ __half g_x16  [BB * 4 * II];   // prologue scratch: Cb fp16 output
__device__ __half g_emb16[BB * EE];
__device__ __half g_cnn16[BB * FF];
__device__ __half g_bufB16[BB * 4 * II];
// transposed fp16 weights
__device__ __half g_UaT[4 * 1024 * 1024];
__device__ __half g_UcT[4 * 1024 * 1024];
__device__ __half g_WaT[4 * 1024 * 512];
__device__ __half g_WcT[4 * 1024 * 1024];
__device__ __half g_CaT[4 * 1024 * 2048];
__device__ __half g_CcT[4 * 1024 * 1024];

// ---------------------------------------------------------------------------
// helpers
// ---------------------------------------------------------------------------
__device__ __forceinline__ uint32_t smem_u32(const void* p) {
    uint32_t a;
    asm("{ .reg .u64 t; cvta.to.shared.u64 t, %1; cvt.u32.u64 %0, t; }" : "=r"(a) : "l"(p));
    return a;
}
__device__ __forceinline__ void cpa16(uint32_t d, const void* s) {
    asm volatile("cp.async.cg.shared.global [%0], [%1], 16;" :: "r"(d), "l"(s));
}
__device__ __forceinline__ void cpa_commit() { asm volatile("cp.async.commit_group;"); }
template <int N>
__device__ __forceinline__ void cpa_wait() {
    asm volatile("cp.async.wait_group %0;" :: "n"(N) : "memory");
}
__device__ __forceinline__ void ldm_x4(uint32_t* r, uint32_t a) {
    asm volatile("ldmatrix.sync.aligned.m8n8.x4.shared.b16 {%0,%1,%2,%3}, [%4];"
                 : "=r"(r[0]), "=r"(r[1]), "=r"(r[2]), "=r"(r[3]) : "r"(a));
}
__device__ __forceinline__ void mma16816(float* d, const uint32_t* a, uint32_t b0, uint32_t b1) {
    asm volatile(
        "mma.sync.aligned.m16n8k16.row.col.f32.f16.f16.f32 "
        "{%0,%1,%2,%3},{%4,%5,%6,%7},{%8,%9},{%0,%1,%2,%3};"
        : "+f"(d[0]), "+f"(d[1]), "+f"(d[2]), "+f"(d[3])
        : "r"(a[0]), "r"(a[1]), "r"(a[2]), "r"(a[3]), "r"(b0), "r"(b1));
}
__device__ __forceinline__ void pdl_wait()    { asm volatile("griddepcontrol.wait;" ::: "memory"); }
__device__ __forceinline__ void pdl_trigger() { asm volatile("griddepcontrol.launch_dependents;"); }

// ---------------------------------------------------------------------------
// zero state
// ---------------------------------------------------------------------------
__global__ __launch_bounds__(256) void zero_hc_kernel() {
    int idx = blockIdx.x * 256 + threadIdx.x;
    if (idx < BB * HH) {
        g_c[idx] = 0.f;
        g_h16[idx] = __float2half(0.f);
    }
}

// ---------------------------------------------------------------------------
// gather emb = embed[captions[:,0]]  (int64/int32 robust)
// ---------------------------------------------------------------------------
__global__ __launch_bounds__(256) void gather_emb_kernel(const void* __restrict__ caps,
                                                         const float* __restrict__ embed) {
    __shared__ int is64;
    if (threadIdx.x == 0) {
        const int* p = (const int*)caps;
        int z = 1;
        for (int k = 0; k < 16; k++)
            if (p[2 * k + 1] != 0) z = 0;
        is64 = z;
    }
    __syncthreads();
    int idx = blockIdx.x * 256 + threadIdx.x;
    if (idx >= BB * (EE / 4)) return;
    int b  = idx / (EE / 4);
    int e4 = idx % (EE / 4);
    long long cap;
    if (is64) cap = ((const long long*)caps)[(long long)b * TT];
    else      cap = (long long)((const int*)caps)[b * TT];
    float4 v = ((const float4*)embed)[cap * (EE / 4) + e4];
    ((float4*)g_emb)[idx] = v;
}

// ---------------------------------------------------------------------------
// elementwise fp32 -> fp16
// ---------------------------------------------------------------------------
__global__ __launch_bounds__(256) void conv16_kernel(const float* __restrict__ s,
                                                     __half* __restrict__ d) {
    int idx = (blockIdx.x * 256 + threadIdx.x) * 4;
    float4 v = *(const float4*)&s[idx];
    *(__half2*)&d[idx]     = __floats2half2_rn(v.x, v.y);
    *(__half2*)&d[idx + 2] = __floats2half2_rn(v.z, v.w);
}

// ---------------------------------------------------------------------------
// transpose + fp16: dst[g, x, y] = fp16(src[g, y, x]); src (g, K, 1024)
// ---------------------------------------------------------------------------
__global__ __launch_bounds__(256) void convTK_kernel(const float* __restrict__ src,
                                                     __half* __restrict__ dst, int K) {
    __shared__ float t[32][33];
    int g  = blockIdx.z;
    int x0 = blockIdx.x * 32;
    int y0 = blockIdx.y * 32;
    int tx = threadIdx.x & 31, ty = threadIdx.x >> 5;
    const float* s = src + (size_t)g * K * 1024;
#pragma unroll
    for (int k = 0; k < 4; k++)
        t[ty + k * 8][tx] = s[(size_t)(y0 + ty + k * 8) * 1024 + x0 + tx];
    __syncthreads();
    __half* o = dst + (size_t)g * 1024 * K;
#pragma unroll
    for (int k = 0; k < 4; k++)
        o[(size_t)(x0 + ty + k * 8) * K + y0 + tx] = __float2half(t[tx][ty + k * 8]);
}

// ---------------------------------------------------------------------------
// fp32 prologue SGEMM core (K=300 GEMMs), shared by single and dual kernels
// mode 0: C=acc (fp32) ; mode 1: Ch=fp16(acc * Z)
// ---------------------------------------------------------------------------
#define BM 64
#define BN 128
#define BK 16

__device__ __forceinline__ void gemm4_body(
    const float* __restrict__ A, int lda,
    const float* __restrict__ Wg, int K, int g, int bx, int by,
    const float* Z, float* C, __half* Ch, int mode)
{
    __shared__ float As[BK][BM];
    __shared__ float Bs[BK][BN];

    const int N = 1024;
    const int tid = threadIdx.x;
    const int tx  = tid & 15;
    const int ty  = tid >> 4;

    float acc[4][8];
#pragma unroll
    for (int i = 0; i < 4; i++)
#pragma unroll
        for (int j = 0; j < 8; j++) acc[i][j] = 0.f;

    const int arow = tid >> 2;
    const int ac   = (tid & 3) * 4;

    for (int kk = 0; kk < K; kk += BK) {
        {
            const int m = by * BM + arow;
            const float* ap = A + (size_t)m * lda + kk + ac;
#pragma unroll
            for (int j = 0; j < 4; j++) {
                float v = (kk + ac + j < K) ? ap[j] : 0.f;
                As[ac + j][arow] = v;
            }
        }
#pragma unroll
        for (int r = 0; r < 2; r++) {
            int idx  = tid + r * 256;
            int brow = idx >> 5;
            int bc   = (idx & 31) * 4;
            int kg   = kk + brow;
            float4 v;
            if (kg < K) v = *(const float4*)(Wg + (size_t)kg * N + bc);
            else        v = make_float4(0.f, 0.f, 0.f, 0.f);
            *(float4*)&Bs[brow][bc] = v;
        }
        __syncthreads();

#pragma unroll
        for (int k = 0; k < BK; k++) {
            float4 av = *(const float4*)&As[k][ty * 4];
            float4 b0 = *(const float4*)&Bs[k][tx * 8];
            float4 b1 = *(const float4*)&Bs[k][tx * 8 + 4];
            float a[4] = {av.x, av.y, av.z, av.w};
            float b[8] = {b0.x, b0.y, b0.z, b0.w, b1.x, b1.y, b1.z, b1.w};
#pragma unroll
            for (int i = 0; i < 4; i++)
#pragma unroll
                for (int j = 0; j < 8; j++)
                    acc[i][j] = fmaf(a[i], b[j], acc[i][j]);
        }
        __syncthreads();
    }

#pragma unroll
    for (int i = 0; i < 4; i++) {
        const int m = by * BM + ty * 4 + i;
        const int n0 = bx * BN + tx * 8;
        size_t row = (size_t)m * 4096 + (size_t)g * 1024 + n0;
#pragma unroll
        for (int j = 0; j < 8; j++) {
            float v = acc[i][j];
            if (mode == 1) Ch[row + j] = __float2half(v * Z[row + j]);
            else           C[row + j]  = v;
        }
    }
}

// single-problem version (Ub -> SH, mode 0)
__global__ __launch_bounds__(256) void gemm4_kernel(
    const float* __restrict__ A, int lda,
    const float* __restrict__ W, int K,
    const float* Z, float* C, __half* Ch, int mode)
{
    const int g = blockIdx.z;
    gemm4_body(A, lda, W + (size_t)g * K * 1024 + blockIdx.x * BN, K,
               g, blockIdx.x, blockIdx.y, Z, C, Ch, mode);
}

// dual version: z<4 -> (Wb, Z0, Ch0), z>=4 -> (Cb, Z1, Ch1); mode 1 both
__global__ __launch_bounds__(256) void gemm4_dual_kernel(
    const float* __restrict__ A, int lda, int K,
    const float* __restrict__ W0, const float* __restrict__ W1,
    const float* Z0, const float* Z1,
    __half* Ch0, __half* Ch1)
{
    const int z   = blockIdx.z;
    const int g   = z & 3;
    const int sel = z >> 2;
    const float* W  = (sel ? W1 : W0) + (size_t)g * K * 1024 + blockIdx.x * BN;
    gemm4_body(A, lda, W, K, g, blockIdx.x, blockIdx.y,
               sel ? Z1 : Z0, nullptr, sel ? Ch1 : Ch0, 1);
}

// ---------------------------------------------------------------------------
// shared TC tile geometry — 3-stage pipeline (R12, proven optimum)
// ---------------------------------------------------------------------------
#define ASTRIDE  144                     // bytes per smem row (64 fp16 + pad)
#define A_TILE_B (128 * ASTRIDE)         // 18432
#define B_TILE_B (128 * ASTRIDE)         // 18432
#define STAGE_B  (A_TILE_B + B_TILE_B)   // 36864
#define NSTAGE   3
#define MM_SMEM  (NSTAGE * STAGE_B)      // 110592

__device__ __forceinline__ void load_stage(
    uint32_t sa, uint32_t sb,
    const __half* __restrict__ A, int lda,
    const __half* __restrict__ B, int ldb,
    int k0, int tid)
{
#pragma unroll
    for (int r = 0; r < 4; r++) {
        int id  = tid + (r << 8);
        int row = id >> 3;
        int cb  = id & 7;
        uint32_t d = sa + row * ASTRIDE + cb * 16;
        size_t  sp = (size_t)row * lda + k0 + cb * 8;
        cpa16(d, A + sp);
    }
#pragma unroll
    for (int r = 0; r < 4; r++) {
        int id  = tid + (r << 8);
        int row = id >> 3;
        int cb  = id & 7;
        uint32_t d = sb + row * ASTRIDE + cb * 16;
        size_t  sp = (size_t)row * ldb + k0 + cb * 8;
        cpa16(d, B + sp);
    }
}

__device__ __forceinline__ void chunk_mma(uint32_t aCur, uint32_t bCur, float acc[2][8][4]) {
#pragma unroll
    for (int ks = 0; ks < 4; ks++) {
        uint32_t a[2][4], b[4][4];
        const uint32_t ka = aCur + ks * 32;
        const uint32_t kb = bCur + ks * 32;
        ldm_x4(a[0], ka);
        ldm_x4(a[1], ka + 16 * ASTRIDE);
        ldm_x4(b[0], kb);
        ldm_x4(b[1], kb + 16 * ASTRIDE);
        ldm_x4(b[2], kb + 32 * ASTRIDE);
        ldm_x4(b[3], kb + 48 * ASTRIDE);
#pragma unroll
        for (int im = 0; im < 2; im++)
#pragma unroll
            for (int jn = 0; jn < 8; jn++) {
                const int jp = jn >> 1, q = (jn & 1) * 2;
                mma16816(acc[im][jn], a[im], b[jp][q], b[jp][q + 1]);
            }
    }
}

// 3-stage mainloop: preload 2 chunks; per chunk: wait, ONE sync, prefetch c+2, mma
__device__ __forceinline__ void mainloop3(
    uint32_t sbase, const __half* Ap, int lda, const __half* Bp, int ldb,
    int NC, int tid, uint32_t aBase, uint32_t bBase, float acc[2][8][4])
{
    load_stage(sbase,           sbase + A_TILE_B,           Ap, lda, Bp, ldb, 0,  tid);
    cpa_commit();
    load_stage(sbase + STAGE_B, sbase + STAGE_B + A_TILE_B, Ap, lda, Bp, ldb, 64, tid);
    cpa_commit();

    for (int c = 0; c < NC; c++) {
        if (c + 1 < NC) cpa_wait<1>(); else cpa_wait<0>();
        __syncthreads();
        if (c + 2 < NC) {
            const uint32_t s2 = ((c + 2) % NSTAGE) * STAGE_B;
            load_stage(sbase + s2, sbase + s2 + A_TILE_B, Ap, lda, Bp, ldb, (c + 2) * 64, tid);
            cpa_commit();
        }
        const uint32_t soff = (c % NSTAGE) * STAGE_B;
        chunk_mma(aBase + soff, bBase + soff, acc);
    }
}

// ---------------------------------------------------------------------------
// Recurrence split-K GEMM: grid (8 nx, 4 {my,kh}, 4 g) = 128 CTAs
// ---------------------------------------------------------------------------
__global__ __launch_bounds__(256, 1) void tcsplit_kernel(
    const __half* __restrict__ A, int lda, int agoff,
    const __half* __restrict__ B,
    float* __restrict__ part0, float* __restrict__ part1)
{
    extern __shared__ char dsm[];
    const uint32_t sbase = smem_u32(dsm);

    const int g    = blockIdx.z;
    const int nx   = blockIdx.x;
    const int my   = blockIdx.y >> 1;
    const int kh   = blockIdx.y & 1;
    const int tid  = threadIdx.x;
    const int lane = tid & 31;
    const int warp = tid >> 5;
    const int wm   = warp & 3;
    const int wn   = warp >> 2;

    pdl_wait();

    const __half* Ap = A + (size_t)g * agoff + (size_t)(my * 128) * lda + kh * 512;
    const __half* Bp = B + ((size_t)g * 1024 + nx * 128) * 1024 + kh * 512;
    float* outP = kh ? part1 : part0;

    float acc[2][8][4];
#pragma unroll
    for (int i = 0; i < 2; i++)
#pragma unroll
        for (int j = 0; j < 8; j++)
#pragma unroll
            for (int k = 0; k < 4; k++) acc[i][j][k] = 0.f;

    const int rin  = lane & 7;
    const int quad = lane >> 3;
    const uint32_t aoff = ((quad & 1) * 8 + rin) * ASTRIDE + (quad >> 1) * 16;
    const uint32_t boff = ((quad >> 1) * 8 + rin) * ASTRIDE + (quad & 1) * 16;
    const uint32_t aBase = sbase + wm * 32 * ASTRIDE + aoff;
    const uint32_t bBase = sbase + A_TILE_B + wn * 64 * ASTRIDE + boff;

    mainloop3(sbase, Ap, lda, Bp, 1024, 8, tid, aBase, bBase, acc);

#pragma unroll
    for (int im = 0; im < 2; im++) {
        const int m0 = my * 128 + wm * 32 + im * 16 + (lane >> 2);
#pragma unroll
        for (int jn = 0; jn < 8; jn++) {
            const int n0 = nx * 128 + wn * 64 + jn * 8 + (lane & 3) * 2;
            const size_t p0 = (size_t)m0 * 4096 + (size_t)g * 1024 + n0;
            const size_t p1 = p0 + 8 * 4096;
            const float* a = acc[im][jn];
            *(float2*)&outP[p0] = make_float2(a[0], a[1]);
            *(float2*)&outP[p1] = make_float2(a[2], a[3]);
        }
    }
    pdl_trigger();
}

// ---------------------------------------------------------------------------
// Prologue TC GEMM: runtime K (mult of 64, NC>=8). grid (8 nx, 2 my, 4 g).
// mode 0: C=acc ; mode 2: C=acc+Z+bias.
// ---------------------------------------------------------------------------
__global__ __launch_bounds__(256, 1) void tcpro_kernel(
    const __half* __restrict__ A, int lda, int agoff,
    const __half* __restrict__ BT, int K,
    const float* Z, const float* __restrict__ bias,
    float* __restrict__ outF, int mode)
{
    extern __shared__ char dsm[];
    const uint32_t sbase = smem_u32(dsm);

    const int g    = blockIdx.z;
    const int nx   = blockIdx.x;
    const int my   = blockIdx.y;
    const int tid  = threadIdx.x;
    const int lane = tid & 31;
    const int warp = tid >> 5;
    const int wm   = warp & 3;
    const int wn   = warp >> 2;

    const __half* Ap = A + (size_t)g * agoff + (size_t)(my * 128) * lda;
    const __half* Bp = BT + ((size_t)g * 1024 + nx * 128) * K;

    float acc[2][8][4];
#pragma unroll
    for (int i = 0; i < 2; i++)
#pragma unroll
        for (int j = 0; j < 8; j++)
#pragma unroll
            for (int k = 0; k < 4; k++) acc[i][j][k] = 0.f;

    const int rin  = lane & 7;
    const int quad = lane >> 3;
    const uint32_t aoff = ((quad & 1) * 8 + rin) * ASTRIDE + (quad >> 1) * 16;
    const uint32_t boff = ((quad >> 1) * 8 + rin) * ASTRIDE + (quad & 1) * 16;
    const uint32_t aBase = sbase + wm * 32 * ASTRIDE + aoff;
    const uint32_t bBase = sbase + A_TILE_B + wn * 64 * ASTRIDE + boff;

    mainloop3(sbase, Ap, lda, Bp, K, K >> 6, tid, aBase, bBase, acc);

#pragma unroll
    for (int im = 0; im < 2; im++) {
        const int m0 = my * 128 + wm * 32 + im * 16 + (lane >> 2);
#pragma unroll
        for (int jn = 0; jn < 8; jn++) {
            const int n0 = nx * 128 + wn * 64 + jn * 8 + (lane & 3) * 2;
            const size_t p0 = (size_t)m0 * 4096 + (size_t)g * 1024 + n0;
            const size_t p1 = p0 + 8 * 4096;
            const float* a = acc[im][jn];
            if (mode == 2) {
                float b0 = bias[g * 1024 + n0], b1 = bias[g * 1024 + n0 + 1];
                *(float2*)&outF[p0] = make_float2(a[0] + Z[p0] + b0, a[1] + Z[p0 + 1] + b1);
                *(float2*)&outF[p1] = make_float2(a[2] + Z[p1] + b0, a[3] + Z[p1 + 1] + b1);
            } else {
                *(float2*)&outF[p0] = make_float2(a[0], a[1]);
                *(float2*)&outF[p1] = make_float2(a[2], a[3]);
            }
        }
    }
}

// ---------------------------------------------------------------------------
// E1: x16 = fp16((p0 + p1) * SH)
// ---------------------------------------------------------------------------
__global__ __launch_bounds__(256) void e1_kernel() {
    pdl_wait();
    int idx = (blockIdx.x * 256 + threadIdx.x) * 4;
    float4 a = *(const float4*)&g_p0[idx];
    float4 b = *(const float4*)&g_p1[idx];
    float4 s = *(const float4*)&g_SH[idx];
    *(__half2*)&g_x16[idx]     = __floats2half2_rn((a.x + b.x) * s.x, (a.y + b.y) * s.y);
    *(__half2*)&g_x16[idx + 2] = __floats2half2_rn((a.z + b.z) * s.z, (a.w + b.w) * s.w);
    pdl_trigger();
}

// ---------------------------------------------------------------------------
// LSTM gate update (float4): pre = p0+p1+base; updates c, h fp16
// ---------------------------------------------------------------------------
__global__ __launch_bounds__(256) void lstm_gate_kernel(float* out) {
    pdl_wait();
    int idx = (blockIdx.x * 256 + threadIdx.x) * 4;
    int b   = idx >> 10;
    int hh  = idx & 1023;
    size_t off = ((size_t)b << 12) + hh;

    float4 i0 = *(const float4*)&g_p0[off];
    float4 i1 = *(const float4*)&g_p1[off];
    float4 ib = *(const float4*)&g_base[off];
    float4 f0 = *(const float4*)&g_p0[off + 1024];
    float4 f1 = *(const float4*)&g_p1[off + 1024];
    float4 fb = *(const float4*)&g_base[off + 1024];
    float4 o0 = *(const float4*)&g_p0[off + 2048];
    float4 o1 = *(const float4*)&g_p1[off + 2048];
    float4 ob = *(const float4*)&g_base[off + 2048];
    float4 q0 = *(const float4*)&g_p0[off + 3072];
    float4 q1 = *(const float4*)&g_p1[off + 3072];
    float4 qb = *(const float4*)&g_base[off + 3072];
    float4 cc = *(const float4*)&g_c[idx];

    float hv[4];
#pragma unroll
    for (int k = 0; k < 4; k++) {
        float xi = ((const float*)&i0)[k] + ((const float*)&i1)[k] + ((const float*)&ib)[k];
        float xf = ((const float*)&f0)[k] + ((const float*)&f1)[k] + ((const float*)&fb)[k];
        float xo = ((const float*)&o0)[k] + ((const float*)&o1)[k] + ((const float*)&ob)[k];
        float xg = ((const float*)&q0)[k] + ((const float*)&q1)[k] + ((const float*)&qb)[k];
        float ig = 1.f / (1.f + expf(-xi));
        float fg = 1.f / (1.f + expf(-xf));
        float og = 1.f / (1.f + expf(-xo));
        float gg = tanhf(xg);
        float c = fg * ((const float*)&cc)[k] + ig * gg;
        ((float*)&cc)[k] = c;
        hv[k] = og * tanhf(c);
    }
    *(float4*)&g_c[idx] = cc;
    *(__half2*)&g_h16[idx]     = __floats2half2_rn(hv[0], hv[1]);
    *(__half2*)&g_h16[idx + 2] = __floats2half2_rn(hv[2], hv[3]);
    if (out) *(float4*)&out[idx] = make_float4(hv[0], hv[1], hv[2], hv[3]);
    pdl_trigger();
}

// ---------------------------------------------------------------------------
extern "C" void kernel_launch(void* const* d_in, const int* in_sizes, int n_in,
                              void* d_out, int out_size) {
    const void*  caps  = d_in[0];
    const float* cnn   = (const float*)d_in[1];
    const float* sem   = (const float*)d_in[2];
    const float* embed = (const float*)d_in[3];
    const float* Wa    = (const float*)d_in[4];
    const float* Wb    = (const float*)d_in[5];
    const float* Wc    = (const float*)d_in[6];
    const float* Ua    = (const float*)d_in[7];
    const float* Ub    = (const float*)d_in[8];
    const float* Uc    = (const float*)d_in[9];
    const float* Ca    = (const float*)d_in[10];
    const float* Cb    = (const float*)d_in[11];
    const float* Cc    = (const float*)d_in[12];
    const float* bias  = (const float*)d_in[13];

    float *p_emb, *p_bufA, *p_base, *p_SH, *p_p0, *p_p1;
    cudaGetSymbolAddress((void**)&p_emb,  g_emb);
    cudaGetSymbolAddress((void**)&p_bufA, g_bufA);
    cudaGetSymbolAddress((void**)&p_base, g_base);
    cudaGetSymbolAddress((void**)&p_SH,   g_SH);
    cudaGetSymbolAddress((void**)&p_p0,   g_p0);
    cudaGetSymbolAddress((void**)&p_p1,   g_p1);

    __half *p_h16, *p_x16, *p_emb16, *p_cnn16, *p_bufB16;
    __half *p_UaT, *p_UcT, *p_WaT, *p_WcT, *p_CaT, *p_CcT;
    cudaGetSymbolAddress((void**)&p_h16,   g_h16);
    cudaGetSymbolAddress((void**)&p_x16,   g_x16);
    cudaGetSymbolAddress((void**)&p_emb16, g_emb16);
    cudaGetSymbolAddress((void**)&p_cnn16, g_cnn16);
    cudaGetSymbolAddress((void**)&p_bufB16,g_bufB16);
    cudaGetSymbolAddress((void**)&p_UaT, g_UaT);
    cudaGetSymbolAddress((void**)&p_UcT, g_UcT);
    cudaGetSymbolAddress((void**)&p_WaT, g_WaT);
    cudaGetSymbolAddress((void**)&p_WcT, g_WcT);
    cudaGetSymbolAddress((void**)&p_CaT, g_CaT);
    cudaGetSymbolAddress((void**)&p_CcT, g_CcT);

    cudaFuncSetAttribute(tcsplit_kernel, cudaFuncAttributeMaxDynamicSharedMemorySize, MM_SMEM);
    cudaFuncSetAttribute(tcpro_kernel,   cudaFuncAttributeMaxDynamicSharedMemorySize, MM_SMEM);

    dim3 gg(1024 / BN, BB / BM, 4);   // fp32 GEMM grid (Ub)
    dim3 gd(1024 / BN, BB / BM, 8);   // dual fp32 GEMM grid (Wb+Cb)
    dim3 pg(8, 2, 4);                 // prologue TC grid (64 CTAs)

    zero_hc_kernel<<<(BB * HH + 255) / 256, 256>>>();
    gather_emb_kernel<<<(BB * EE / 4 + 255) / 256, 256>>>(caps, embed);
    conv16_kernel<<<BB * EE / 1024, 256>>>(p_emb, p_emb16);
    conv16_kernel<<<BB * FF / 1024, 256>>>(cnn, p_cnn16);

    // weight transposes + fp16
    convTK_kernel<<<dim3(32, 32, 4), 256>>>(Ua, p_UaT, 1024);
    convTK_kernel<<<dim3(32, 32, 4), 256>>>(Uc, p_UcT, 1024);
    convTK_kernel<<<dim3(32, 16, 4), 256>>>(Wa, p_WaT, 512);
    convTK_kernel<<<dim3(32, 32, 4), 256>>>(Wc, p_WcT, 1024);
    convTK_kernel<<<dim3(32, 64, 4), 256>>>(Ca, p_CaT, 2048);
    convTK_kernel<<<dim3(32, 32, 4), 256>>>(Cc, p_CcT, 1024);

    // prologue:
    //   bufA = emb@Wa ; p0 = cnn@Ca            (independent TC GEMMs)
    //   dual: bufB16 = fp16(sem@Wb * bufA) ; x16 = fp16(sem@Cb * p0)
    //   base = bufB16@Wc ; base += x16@Cc + bias ; SH = sem@Ub
    tcpro_kernel<<<pg, 256, MM_SMEM>>>(p_emb16, EE, 0, p_WaT, EE, nullptr, nullptr, p_bufA, 0);
    tcpro_kernel<<<pg, 256, MM_SMEM>>>(p_cnn16, FF, 0, p_CaT, FF, nullptr, nullptr, p_p0, 0);
    gemm4_dual_kernel<<<gd, 256>>>(sem, LL, LL, Wb, Cb, p_bufA, p_p0, p_bufB16, p_x16);
    tcpro_kernel<<<pg, 256, MM_SMEM>>>(p_bufB16, 4096, 1024, p_WcT, II, nullptr, nullptr, p_base, 0);
    tcpro_kernel<<<pg, 256, MM_SMEM>>>(p_x16,   4096, 1024, p_CcT, II, p_base, bias, p_base, 2);
    gemm4_kernel<<<gg, 256>>>(sem, LL, Ub, LL, nullptr, p_SH, nullptr, 0);

    // PDL launch configs for the recurrence loop
    cudaLaunchAttribute at[1];
    at[0].id = cudaLaunchAttributeProgrammaticStreamSerialization;
    at[0].val.programmaticStreamSerializationAllowed = 1;

    cudaLaunchConfig_t cfgG = {};
    cfgG.gridDim = dim3(8, 4, 4); cfgG.blockDim = dim3(256);
    cfgG.dynamicSmemBytes = MM_SMEM;
    cfgG.attrs = at; cfgG.numAttrs = 1;

    cudaLaunchConfig_t cfgE = {};
    cfgE.gridDim = dim3(BB * 4 * II / (256 * 4)); cfgE.blockDim = dim3(256);
    cfgE.attrs = at; cfgE.numAttrs = 1;

    cudaLaunchConfig_t cfgL = {};
    cfgL.gridDim = dim3(BB * HH / (256 * 4)); cfgL.blockDim = dim3(256);
    cfgL.attrs = at; cfgL.numAttrs = 1;

    for (int t = 0; t < TT; t++) {
        cudaLaunchKernelEx(&cfgG, tcsplit_kernel,
                           (const __half*)p_h16, 1024, 0, (const __half*)p_UaT, p_p0, p_p1);
        cudaLaunchKernelEx(&cfgE, e1_kernel);
        cudaLaunchKernelEx(&cfgG, tcsplit_kernel,
                           (const __half*)p_x16, 4096, 1024, (const __half*)p_UcT, p_p0, p_p1);
        cudaLaunchKernelEx(&cfgL, lstm_gate_kernel,
                           (float*)(t == TT - 1 ? d_out : nullptr));
    }
}